// round 3
// baseline (speedup 1.0000x reference)
#include <cuda_runtime.h>
#include <stdint.h>

#define BATCH 4
#define HEADS 32
#define SEQ   4096
#define DK    128
#define HALF  (DK / 2)            // 64 rotation pairs
#define VEC_PER_ROW (DK / 4)      // 32 float4 per d_k row
#define BH (BATCH * HEADS)        // 128 batch-head slices
#define PLANE (SEQ * VEC_PER_ROW) // 131072 float4 per bh slice

// Fused kernel: block b handles sequence position s = b, all 128 bh slices.
// Phase 1: gather 64 (c,s) pairs from block-diagonal R into smem.
// Phase 2: stream x -> out with rotation, 16 float4 per thread, MLP-4.
__global__ void __launch_bounds__(256)
rope_fused(const float4* __restrict__ x, float4* __restrict__ out,
           const float* __restrict__ R, const int* __restrict__ tp) {
    __shared__ float4 cs_sh[VEC_PER_ROW];   // (c0,s0,c1,s1) x 32

    const int s = blockIdx.x;
    const int t = threadIdx.x;

    if (t < HALF) {
        long long pos = tp[s];
        const float* Rp = R + pos * (long long)(DK * DK);
        int p = t;
        float c  = __ldg(&Rp[(2 * p) * DK + 2 * p]);
        float sv = __ldg(&Rp[(2 * p + 1) * DK + 2 * p]);
        reinterpret_cast<float2*>(cs_sh)[p] = make_float2(c, sv);
    }
    __syncthreads();

    const int lane = t & 31;
    const int w    = t >> 5;                 // warp 0..7

    const float4 cs = cs_sh[lane];           // invariant per thread

    // Base float4 index for this thread at bh=0: bh*PLANE + s*32 + lane
    const size_t row = (size_t)s * VEC_PER_ROW + lane;

    #define ROT(o, xi)                               \
        o.x = fmaf(cs.x, xi.x, -cs.y * xi.y);        \
        o.y = fmaf(cs.y, xi.x,  cs.x * xi.y);        \
        o.z = fmaf(cs.z, xi.z, -cs.w * xi.w);        \
        o.w = fmaf(cs.w, xi.z,  cs.z * xi.w);

    // 16 bh-slices per thread (bh = g*32 + j*8 + w), grouped MLP-4.
    #pragma unroll
    for (int g = 0; g < 4; g++) {
        size_t i0 = row + (size_t)(g * 32 + 0 * 8 + w) * PLANE;
        size_t i1 = row + (size_t)(g * 32 + 1 * 8 + w) * PLANE;
        size_t i2 = row + (size_t)(g * 32 + 2 * 8 + w) * PLANE;
        size_t i3 = row + (size_t)(g * 32 + 3 * 8 + w) * PLANE;

        float4 x0 = __ldcs(&x[i0]);
        float4 x1 = __ldcs(&x[i1]);
        float4 x2 = __ldcs(&x[i2]);
        float4 x3 = __ldcs(&x[i3]);

        float4 o0, o1, o2, o3;
        ROT(o0, x0) ROT(o1, x1) ROT(o2, x2) ROT(o3, x3)

        __stcs(&out[i0], o0);
        __stcs(&out[i1], o1);
        __stcs(&out[i2], o2);
        __stcs(&out[i3], o3);
    }
    #undef ROT
}

extern "C" void kernel_launch(void* const* d_in, const int* in_sizes, int n_in,
                              void* d_out, int out_size) {
    const float* x  = (const float*)d_in[0];
    const int*   tp = (const int*)d_in[1];
    const float* R  = (const float*)d_in[2];
    float* out = (float*)d_out;

    rope_fused<<<SEQ, 256>>>((const float4*)x, (float4*)out, R, tp);
}

// round 4
// speedup vs baseline: 1.0990x; 1.0990x over previous
#include <cuda_runtime.h>
#include <stdint.h>

#define BATCH 4
#define HEADS 32
#define SEQ   4096
#define DK    128
#define HALF  (DK / 2)            // 64 rotation pairs
#define VEC_PER_ROW (DK / 4)      // 32 float4 per d_k row
#define BH (BATCH * HEADS)        // 128 batch-head slices
#define BH_PER_THREAD 8
#define PLANE (SEQ * VEC_PER_ROW) // 131072 float4 per bh slice

// 2 MB scratch: per (seq position, float4-group) -> (c0, s0, c1, s1)
__device__ float4 g_cs[SEQ * VEC_PER_ROW];

// Kernel A: gather cos/sin from block-diagonal R via token_positions.
// KEY: c and -s are ADJACENT in row 2p:  R[pos, 2p, 2p] = c, R[pos, 2p, 2p+1] = -s.
// One aligned float2 load per pair (single 32B sector).
__global__ void build_cs_table(const float* __restrict__ R,
                               const int* __restrict__ token_positions) {
    int tid = blockIdx.x * blockDim.x + threadIdx.x;   // over SEQ * HALF
    if (tid >= SEQ * HALF) return;
    int p = tid & (HALF - 1);
    int s = tid >> 6;
    long long pos = token_positions[s];
    // element offset = pos*128*128 + (2p)*128 + 2p  (even -> float2 aligned)
    const float2* cm = reinterpret_cast<const float2*>(
        R + pos * (long long)(DK * DK) + (2 * p) * DK + 2 * p);
    float2 v = __ldg(cm);            // (c, -s)
    float2* cs2 = reinterpret_cast<float2*>(g_cs);
    cs2[s * HALF + p] = make_float2(v.x, -v.y);   // store (c, s)
}

// Kernel B: each thread handles one (s, d4) slot across 8 batch-head slices.
// 1 table load (L2-resident), 8 front-batched streamed loads, 8 streamed stores.
__global__ void __launch_bounds__(256)
rope_kernel(const float4* __restrict__ x, float4* __restrict__ out) {
    unsigned t = blockIdx.x * blockDim.x + threadIdx.x;  // 0 .. 2,097,151
    unsigned r   = t & (PLANE - 1);                      // (s, d4) within a slice
    unsigned bh8 = t >> 17;                              // group of 8 slices (0..15)

    float4 cs = g_cs[r];                                 // L2 hit (2 MB table)

    unsigned base = bh8 * (8u * PLANE) + r;

    float4 xv[BH_PER_THREAD];
    #pragma unroll
    for (int j = 0; j < BH_PER_THREAD; j++)
        xv[j] = __ldcs(&x[base + (unsigned)j * PLANE]);

    #pragma unroll
    for (int j = 0; j < BH_PER_THREAD; j++) {
        float4 o;
        o.x = fmaf(cs.x, xv[j].x, -cs.y * xv[j].y);
        o.y = fmaf(cs.y, xv[j].x,  cs.x * xv[j].y);
        o.z = fmaf(cs.z, xv[j].z, -cs.w * xv[j].w);
        o.w = fmaf(cs.w, xv[j].z,  cs.z * xv[j].w);
        __stcs(&out[base + (unsigned)j * PLANE], o);
    }
}

extern "C" void kernel_launch(void* const* d_in, const int* in_sizes, int n_in,
                              void* d_out, int out_size) {
    const float* x  = (const float*)d_in[0];
    const int*   tp = (const int*)d_in[1];
    const float* R  = (const float*)d_in[2];
    float* out = (float*)d_out;

    build_cs_table<<<(SEQ * HALF + 255) / 256, 256>>>(R, tp);

    // threads = (BH/8) * PLANE = 16 * 131072 = 2,097,152 -> 8192 blocks
    unsigned total_threads = (BH / BH_PER_THREAD) * PLANE;
    rope_kernel<<<total_threads / 256, 256>>>((const float4*)x, (float4*)out);
}

// round 5
// speedup vs baseline: 1.1186x; 1.0178x over previous
#include <cuda_runtime.h>
#include <stdint.h>

#define BATCH 4
#define HEADS 32
#define SEQ   4096
#define DK    128
#define HALF  (DK / 2)            // 64 rotation pairs
#define VEC_PER_ROW (DK / 4)      // 32 float4 per d_k row
#define BH (BATCH * HEADS)        // 128 batch-head slices
#define PLANE (SEQ * VEC_PER_ROW) // 131072 float4 per bh slice

// 2 MB scratch: per (seq position, float4-group) -> (c0, s0, c1, s1)
__device__ float4 g_cs[SEQ * VEC_PER_ROW];

// Kernel A: gather cos/sin from block-diagonal R via token_positions.
// c and -s are ADJACENT:  R[pos, 2p, 2p] = c, R[pos, 2p, 2p+1] = -s
// -> one aligned float2 load per pair.
__global__ void build_cs_table(const float* __restrict__ R,
                               const int* __restrict__ token_positions) {
    int tid = blockIdx.x * blockDim.x + threadIdx.x;   // over SEQ * HALF
    if (tid < SEQ * HALF) {
        int p = tid & (HALF - 1);
        int s = tid >> 6;
        long long pos = token_positions[s];
        const float2* cm = reinterpret_cast<const float2*>(
            R + pos * (long long)(DK * DK) + (2 * p) * DK + 2 * p);
        float2 v = __ldg(cm);            // (c, -s)
        reinterpret_cast<float2*>(g_cs)[s * HALF + p] = make_float2(v.x, -v.y);
    }
    // Allow the dependent rope_kernel grid to launch as soon as this CTA is done.
    cudaTriggerProgrammaticLaunchCompletion();
}

// Kernel B: one (s,d4) slot across 4 bh slices. x loads are independent of the
// table, so they issue BEFORE the grid-dependency sync (overlapping kernel A).
__global__ void __launch_bounds__(256)
rope_kernel(const float4* __restrict__ x, float4* __restrict__ out) {
    unsigned t = blockIdx.x * blockDim.x + threadIdx.x;
    unsigned r   = t & (PLANE - 1);                      // (s, d4) within a slice
    unsigned bh4 = t >> 17;                              // group of 4 slices

    unsigned base = bh4 * (4u * PLANE) + r;

    // Front-batch 4 independent streamed loads (do NOT depend on g_cs).
    float4 x0 = __ldcs(&x[base + 0u * PLANE]);
    float4 x1 = __ldcs(&x[base + 1u * PLANE]);
    float4 x2 = __ldcs(&x[base + 2u * PLANE]);
    float4 x3 = __ldcs(&x[base + 3u * PLANE]);

    // Wait for build_cs_table grid to complete before touching the table.
    cudaGridDependencySynchronize();

    float4 cs = g_cs[r];                                 // L2 hit (2 MB table)

    float4 o0, o1, o2, o3;
    #define ROT(o, xi)                                  \
        o.x = fmaf(cs.x, xi.x, -cs.y * xi.y);           \
        o.y = fmaf(cs.y, xi.x,  cs.x * xi.y);           \
        o.z = fmaf(cs.z, xi.z, -cs.w * xi.w);           \
        o.w = fmaf(cs.w, xi.z,  cs.z * xi.w);
    ROT(o0, x0) ROT(o1, x1) ROT(o2, x2) ROT(o3, x3)
    #undef ROT

    __stcs(&out[base + 0u * PLANE], o0);
    __stcs(&out[base + 1u * PLANE], o1);
    __stcs(&out[base + 2u * PLANE], o2);
    __stcs(&out[base + 3u * PLANE], o3);
}

extern "C" void kernel_launch(void* const* d_in, const int* in_sizes, int n_in,
                              void* d_out, int out_size) {
    const float* x  = (const float*)d_in[0];
    const int*   tp = (const int*)d_in[1];
    const float* R  = (const float*)d_in[2];
    float* out = (float*)d_out;

    build_cs_table<<<(SEQ * HALF + 255) / 256, 256>>>(R, tp);

    // rope: (BH/4) * PLANE = 4,194,304 threads -> 16384 blocks, launched with
    // programmatic dependent launch so it overlaps build_cs_table.
    cudaLaunchConfig_t cfg = {};
    cfg.gridDim  = dim3((BH / 4) * PLANE / 256, 1, 1);
    cfg.blockDim = dim3(256, 1, 1);
    cfg.dynamicSmemBytes = 0;
    cfg.stream = 0;  // legacy default stream, same as <<<>>> above
    cudaLaunchAttribute attr[1];
    attr[0].id = cudaLaunchAttributeProgrammaticStreamSerialization;
    attr[0].val.programmaticStreamSerializationAllowed = 1;
    cfg.attrs = attr;
    cfg.numAttrs = 1;
    cudaLaunchKernelEx(&cfg, rope_kernel, (const float4*)x, (float4*)out);
}